// round 16
// baseline (speedup 1.0000x reference)
#include <cstdint>
#include <cuda_runtime.h>
#include <cuda_bf16.h>

#define NH   6
#define HS   24
#define NE   144
#define TT   128
#define BB   256
#define MTOT (BB*TT)        // 32768 tokens

typedef __nv_bfloat16 bf16;

// ---------------- device scratch (allocation-free, bf16 hi/lo pairs) --------
__device__ bf16 g_qhi[MTOT*NE], g_qlo[MTOT*NE];
__device__ bf16 g_khi[MTOT*NE], g_klo[MTOT*NE];   // pre-scaled by 1/sqrt(hs)
__device__ bf16 g_vhi[MTOT*NE], g_vlo[MTOT*NE];
__device__ bf16 g_chi[MTOT*NE], g_clo[MTOT*NE];   // ctx, split
__device__ bf16 g_wthi[4*NE*NE], g_wtlo[4*NE*NE]; // W^T [n][k], q,k,v,proj
__device__ bf16 g_rhi[255*HS],   g_rlo[255*HS];   // rel_table split

// ---------------- helpers ----------------
__device__ __forceinline__ void mma_bf16(float c[4],
    uint32_t a0, uint32_t a1, uint32_t a2, uint32_t a3,
    uint32_t b0, uint32_t b1)
{
    asm volatile(
        "mma.sync.aligned.m16n8k16.row.col.f32.bf16.bf16.f32 "
        "{%0,%1,%2,%3}, {%4,%5,%6,%7}, {%8,%9}, {%0,%1,%2,%3};"
        : "+f"(c[0]), "+f"(c[1]), "+f"(c[2]), "+f"(c[3])
        : "r"(a0), "r"(a1), "r"(a2), "r"(a3), "r"(b0), "r"(b1));
}

__device__ __forceinline__ void split2(float v0, float v1, uint32_t& hi, uint32_t& lo)
{
    bf16 h0 = __float2bfloat16(v0), h1 = __float2bfloat16(v1);
    float r0 = v0 - __bfloat162float(h0), r1 = v1 - __bfloat162float(h1);
    hi = ((uint32_t)__bfloat16_as_ushort(h1) << 16) | __bfloat16_as_ushort(h0);
    lo = ((uint32_t)__bfloat16_as_ushort(__float2bfloat16(r1)) << 16)
       |  (uint32_t)__bfloat16_as_ushort(__float2bfloat16(r0));
}

// =====================================================================
// Setup: weight transpose+split and rel_table split (small)
// =====================================================================
__global__ __launch_bounds__(256) void split_wr_kernel(
    const float* __restrict__ Wq, const float* __restrict__ Wk,
    const float* __restrict__ Wv, const float* __restrict__ Wp,
    const float* __restrict__ rel)
{
    int m = blockIdx.y;
    int i = blockIdx.x * 256 + threadIdx.x;
    if (m < 4) {
        if (i >= NE * NE) return;
        const float* src = (m == 0) ? Wq : (m == 1) ? Wk : (m == 2) ? Wv : Wp;
        int k = i / NE, n = i - k * NE;
        float v = src[i];
        bf16 h = __float2bfloat16(v);
        g_wthi[m * NE * NE + n * NE + k] = h;
        g_wtlo[m * NE * NE + n * NE + k] = __float2bfloat16(v - __bfloat162float(h));
    } else {
        if (i >= 255 * HS) return;
        float v = rel[i];
        bf16 h = __float2bfloat16(v);
        g_rhi[i] = h;
        g_rlo[i] = __float2bfloat16(v - __bfloat162float(h));
    }
}

// =====================================================================
// gemm6: 64-row A tiles, 36-reg accumulators -> 3-4 CTAs/SM.
// 256 threads = 8 warps: warp w -> mrow=(w&3)*16, ncol=(w>>2)*72.
// A resident in smem (one barrier), B fragments straight from global,
// fused 3-term split per k-tile.  smem 38912 B.
// =====================================================================
#define LDA4 152
#define GSM6 (2*64*LDA4*2)   // 38912

__device__ __forceinline__ void gemm6_loop(
    const bf16* __restrict__ Asm_hi, const bf16* __restrict__ Asm_lo,
    const bf16* __restrict__ Wh, const bf16* __restrict__ Wl,
    float acc[9][4], int mrow, int ncol, int g, int t)
{
    #pragma unroll 1
    for (int ks = 0; ks < 9; ++ks) {
        const int k0 = ks * 16;
        const bf16* abh = Asm_hi + (mrow + g) * LDA4 + k0 + 2 * t;
        uint32_t ah0 = *(const uint32_t*)(abh);
        uint32_t ah1 = *(const uint32_t*)(abh + 8 * LDA4);
        uint32_t ah2 = *(const uint32_t*)(abh + 8);
        uint32_t ah3 = *(const uint32_t*)(abh + 8 * LDA4 + 8);
        const bf16* abl = Asm_lo + (mrow + g) * LDA4 + k0 + 2 * t;
        uint32_t al0 = *(const uint32_t*)(abl);
        uint32_t al1 = *(const uint32_t*)(abl + 8 * LDA4);
        uint32_t al2 = *(const uint32_t*)(abl + 8);
        uint32_t al3 = *(const uint32_t*)(abl + 8 * LDA4 + 8);
        #pragma unroll
        for (int nt = 0; nt < 9; ++nt) {
            const int nrow = (ncol + nt * 8 + g) * NE + k0 + 2 * t;
            uint32_t bh0 = *(const uint32_t*)(Wh + nrow);
            uint32_t bh1 = *(const uint32_t*)(Wh + nrow + 8);
            uint32_t bl0 = *(const uint32_t*)(Wl + nrow);
            uint32_t bl1 = *(const uint32_t*)(Wl + nrow + 8);
            mma_bf16(acc[nt], ah0, ah1, ah2, ah3, bh0, bh1);
            mma_bf16(acc[nt], al0, al1, al2, al3, bh0, bh1);
            mma_bf16(acc[nt], ah0, ah1, ah2, ah3, bl0, bl1);
        }
    }
}

__global__ __launch_bounds__(256, 3) void qkv6_kernel(const float* __restrict__ x)
{
    extern __shared__ __align__(16) char smc[];
    bf16* A_hi = (bf16*)smc;                          // [64][152]
    bf16* A_lo = A_hi + 64 * LDA4;

    const int r0 = blockIdx.x * 64;
    const int tid = threadIdx.x;
    const int w = tid >> 5, lane = tid & 31, g = lane >> 2, t = lane & 3;
    const int mrow = (w & 3) * 16, ncol = (w >> 2) * 72;

    // ---- load + split A once (64 x 144 fp32 -> hi/lo bf16) ----
    for (int i = tid; i < 64 * 36; i += 256) {
        int r = i / 36, j = i - r * 36;
        float4 v = *(const float4*)&x[(r0 + r) * NE + j * 4];
        uint32_t h0, l0, h1, l1;
        split2(v.x, v.y, h0, l0);
        split2(v.z, v.w, h1, l1);
        *(uint32_t*)&A_hi[r * LDA4 + j * 4]     = h0;
        *(uint32_t*)&A_hi[r * LDA4 + j * 4 + 2] = h1;
        *(uint32_t*)&A_lo[r * LDA4 + j * 4]     = l0;
        *(uint32_t*)&A_lo[r * LDA4 + j * 4 + 2] = l1;
    }
    __syncthreads();   // the only barrier

    #pragma unroll 1
    for (int z = 0; z < 3; ++z) {
        float acc[9][4];
        #pragma unroll
        for (int nt = 0; nt < 9; ++nt)
            #pragma unroll
            for (int j = 0; j < 4; ++j) acc[nt][j] = 0.f;

        gemm6_loop(A_hi, A_lo, g_wthi + z * NE * NE, g_wtlo + z * NE * NE,
                   acc, mrow, ncol, g, t);

        bf16* ohi = (z == 0) ? g_qhi : (z == 1) ? g_khi : g_vhi;
        bf16* olo = (z == 0) ? g_qlo : (z == 1) ? g_klo : g_vlo;
        const float sc = (z == 1) ? 0.2041241452319315f : 1.f;

        #pragma unroll
        for (int nt = 0; nt < 9; ++nt) {
            int row = r0 + mrow + g;
            int col = ncol + nt * 8 + 2 * t;
            uint32_t h, l;
            split2(acc[nt][0] * sc, acc[nt][1] * sc, h, l);
            *(uint32_t*)&ohi[row * NE + col] = h;
            *(uint32_t*)&olo[row * NE + col] = l;
            split2(acc[nt][2] * sc, acc[nt][3] * sc, h, l);
            *(uint32_t*)&ohi[(row + 8) * NE + col] = h;
            *(uint32_t*)&olo[(row + 8) * NE + col] = l;
        }
    }
}

__global__ __launch_bounds__(256, 3) void proj6_kernel(
    const float* __restrict__ bias, float* __restrict__ out)
{
    extern __shared__ __align__(16) char smc[];
    bf16* A_hi = (bf16*)smc;                          // [64][152]
    bf16* A_lo = A_hi + 64 * LDA4;

    const int r0 = blockIdx.x * 64;
    const int tid = threadIdx.x;
    const int w = tid >> 5, lane = tid & 31, g = lane >> 2, t = lane & 3;
    const int mrow = (w & 3) * 16, ncol = (w >> 2) * 72;

    // ---- copy pre-split ctx A once (hi/lo, 18 uint4 per row) ----
    for (int i = tid; i < 64 * 18; i += 256) {
        int r = i / 18, j = i - r * 18;
        *(uint4*)&A_hi[r * LDA4 + j * 8] = *(const uint4*)&g_chi[(r0 + r) * NE + j * 8];
        *(uint4*)&A_lo[r * LDA4 + j * 8] = *(const uint4*)&g_clo[(r0 + r) * NE + j * 8];
    }
    __syncthreads();   // the only barrier

    float acc[9][4];
    #pragma unroll
    for (int nt = 0; nt < 9; ++nt)
        #pragma unroll
        for (int j = 0; j < 4; ++j) acc[nt][j] = 0.f;

    gemm6_loop(A_hi, A_lo, g_wthi + 3 * NE * NE, g_wtlo + 3 * NE * NE,
               acc, mrow, ncol, g, t);

    #pragma unroll
    for (int nt = 0; nt < 9; ++nt) {
        int row = r0 + mrow + g;
        int col = ncol + nt * 8 + 2 * t;
        float b0v = bias[col], b1v = bias[col + 1];
        out[row * NE + col]           = acc[nt][0] + b0v;
        out[row * NE + col + 1]       = acc[nt][1] + b1v;
        out[(row + 8) * NE + col]     = acc[nt][2] + b0v;
        out[(row + 8) * NE + col + 1] = acc[nt][3] + b1v;
    }
}

// =====================================================================
// Attention v7 (R13/R14-exact): triangular culling, register-resident S.
// =====================================================================
#define VLD   136
#define SLD   132
#define ASMEM5 (128*SLD*4 + 2*24*VLD*2)   // 80640 B

__global__ __launch_bounds__(256, 2) void attn7_kernel()
{
    extern __shared__ __align__(16) char smc[];
    float* P   = (float*)smc;
    bf16* Vthi = (bf16*)(smc + 128 * SLD * 4);
    bf16* Vtlo = Vthi + 24 * VLD;

    const int bh = blockIdx.x;
    const int b = bh / NH, h = bh % NH;
    const int base = b * (TT * NE) + h * (TT * HS);
    const int tid = threadIdx.x;

    {
        const int row = tid >> 1, half = (tid & 1) * 12;
        const int src = base + row * HS + half;
        #pragma unroll
        for (int j = 0; j < 12; ++j) {
            Vthi[(half + j) * VLD + row] = g_vhi[src + j];
            Vtlo[(half + j) * VLD + row] = g_vlo[src + j];
        }
    }
    __syncthreads();

    const int w = tid >> 5, lane = tid & 31, g = lane >> 2, t = lane & 3;
    const int tr  = w * 16 + g;
    const int tr2 = tr + 8;
    const int ntmax = 2 * w + 1;

    float acc[16][4];

    #pragma unroll
    for (int nt = 0; nt < 16; ++nt)
        #pragma unroll
        for (int j = 0; j < 4; ++j) acc[nt][j] = 0.f;

    #pragma unroll 1
    for (int p = 0; p < 3; ++p) {
        const bf16* Ag = ((p == 1) ? g_qlo : g_qhi) + base;
        const bf16* Bg = ((p == 2) ? g_rlo : g_rhi) + 127 * HS;
        const bf16* ab = Ag + tr * HS + 2 * t;
        uint32_t a0 = *(const uint32_t*)(ab);
        uint32_t a1 = *(const uint32_t*)(ab + 8 * HS);
        uint32_t a2 = *(const uint32_t*)(ab + 8);
        uint32_t a3 = *(const uint32_t*)(ab + 8 * HS + 8);
        uint32_t a4 = *(const uint32_t*)(ab + 16);
        uint32_t a5 = *(const uint32_t*)(ab + 8 * HS + 16);
        #pragma unroll
        for (int nt = 0; nt < 16; ++nt) {
            if (nt > ntmax) break;
            const bf16* bb = Bg + (nt * 8 + g) * HS + 2 * t;
            uint32_t b0 = *(const uint32_t*)(bb);
            uint32_t b1 = *(const uint32_t*)(bb + 8);
            uint32_t b2 = *(const uint32_t*)(bb + 16);
            mma_bf16(acc[nt], a0, a1, a2, a3, b0, b1);
            mma_bf16(acc[nt], a4, a5, 0u, 0u, b2, 0u);
        }
    }
    #pragma unroll
    for (int nt = 0; nt < 16; ++nt) {
        if (nt > ntmax) break;
        *(float2*)&P[tr  * SLD + nt * 8 + 2 * t] = make_float2(acc[nt][0], acc[nt][1]);
        *(float2*)&P[tr2 * SLD + nt * 8 + 2 * t] = make_float2(acc[nt][2], acc[nt][3]);
    }
    __syncwarp();

    #pragma unroll
    for (int nt = 0; nt < 16; ++nt)
        #pragma unroll
        for (int j = 0; j < 4; ++j) acc[nt][j] = 0.f;

    #pragma unroll 1
    for (int p = 0; p < 3; ++p) {
        const bf16* Ag = ((p == 1) ? g_qlo : g_qhi) + base;
        const bf16* Bg = ((p == 2) ? g_klo : g_khi) + base;
        const bf16* ab = Ag + tr * HS + 2 * t;
        uint32_t a0 = *(const uint32_t*)(ab);
        uint32_t a1 = *(const uint32_t*)(ab + 8 * HS);
        uint32_t a2 = *(const uint32_t*)(ab + 8);
        uint32_t a3 = *(const uint32_t*)(ab + 8 * HS + 8);
        uint32_t a4 = *(const uint32_t*)(ab + 16);
        uint32_t a5 = *(const uint32_t*)(ab + 8 * HS + 16);
        #pragma unroll
        for (int nt = 0; nt < 16; ++nt) {
            if (nt > ntmax) break;
            const bf16* bb = Bg + (nt * 8 + g) * HS + 2 * t;
            uint32_t b0 = *(const uint32_t*)(bb);
            uint32_t b1 = *(const uint32_t*)(bb + 8);
            uint32_t b2 = *(const uint32_t*)(bb + 16);
            mma_bf16(acc[nt], a0, a1, a2, a3, b0, b1);
            mma_bf16(acc[nt], a4, a5, 0u, 0u, b2, 0u);
        }
    }

    #pragma unroll
    for (int nt = 0; nt < 16; ++nt) {
        int c = nt * 8 + 2 * t;
        acc[nt][0] = (c     <= tr ) ? acc[nt][0] + P[tr  * SLD + tr  - c    ] : -1e30f;
        acc[nt][1] = (c + 1 <= tr ) ? acc[nt][1] + P[tr  * SLD + tr  - c - 1] : -1e30f;
        acc[nt][2] = (c     <= tr2) ? acc[nt][2] + P[tr2 * SLD + tr2 - c    ] : -1e30f;
        acc[nt][3] = (c + 1 <= tr2) ? acc[nt][3] + P[tr2 * SLD + tr2 - c - 1] : -1e30f;
    }

    {
        float m1 = -1e30f, m2 = -1e30f;
        #pragma unroll
        for (int nt = 0; nt < 16; ++nt) {
            m1 = fmaxf(m1, fmaxf(acc[nt][0], acc[nt][1]));
            m2 = fmaxf(m2, fmaxf(acc[nt][2], acc[nt][3]));
        }
        m1 = fmaxf(m1, __shfl_xor_sync(0xffffffffu, m1, 1));
        m1 = fmaxf(m1, __shfl_xor_sync(0xffffffffu, m1, 2));
        m2 = fmaxf(m2, __shfl_xor_sync(0xffffffffu, m2, 1));
        m2 = fmaxf(m2, __shfl_xor_sync(0xffffffffu, m2, 2));
        float s1 = 0.f, s2 = 0.f;
        #pragma unroll
        for (int nt = 0; nt < 16; ++nt) {
            acc[nt][0] = __expf(acc[nt][0] - m1);  s1 += acc[nt][0];
            acc[nt][1] = __expf(acc[nt][1] - m1);  s1 += acc[nt][1];
            acc[nt][2] = __expf(acc[nt][2] - m2);  s2 += acc[nt][2];
            acc[nt][3] = __expf(acc[nt][3] - m2);  s2 += acc[nt][3];
        }
        s1 += __shfl_xor_sync(0xffffffffu, s1, 1);
        s1 += __shfl_xor_sync(0xffffffffu, s1, 2);
        s2 += __shfl_xor_sync(0xffffffffu, s2, 1);
        s2 += __shfl_xor_sync(0xffffffffu, s2, 2);
        float i1 = 1.0f / s1, i2 = 1.0f / s2;
        #pragma unroll
        for (int nt = 0; nt < 16; ++nt) {
            acc[nt][0] *= i1;  acc[nt][1] *= i1;
            acc[nt][2] *= i2;  acc[nt][3] *= i2;
        }
    }

    {
        float cacc[3][4];
        #pragma unroll
        for (int nt = 0; nt < 3; ++nt)
            #pragma unroll
            for (int j = 0; j < 4; ++j) cacc[nt][j] = 0.f;

        #pragma unroll
        for (int ks = 0; ks < 8; ++ks) {
            if (ks > w) break;
            const int k0 = ks * 16;
            uint32_t ah0, al0, ah1, al1, ah2, al2, ah3, al3;
            split2(acc[2*ks][0],   acc[2*ks][1],   ah0, al0);
            split2(acc[2*ks][2],   acc[2*ks][3],   ah1, al1);
            split2(acc[2*ks+1][0], acc[2*ks+1][1], ah2, al2);
            split2(acc[2*ks+1][2], acc[2*ks+1][3], ah3, al3);
            #pragma unroll
            for (int nt = 0; nt < 3; ++nt) {
                const bf16* bhp = Vthi + (nt * 8 + g) * VLD + k0 + 2 * t;
                const bf16* blp = Vtlo + (nt * 8 + g) * VLD + k0 + 2 * t;
                uint32_t bh0 = *(const uint32_t*)(bhp);
                uint32_t bh1 = *(const uint32_t*)(bhp + 8);
                uint32_t bl0 = *(const uint32_t*)(blp);
                uint32_t bl1 = *(const uint32_t*)(blp + 8);
                mma_bf16(cacc[nt], ah0, ah1, ah2, ah3, bh0, bh1);
                mma_bf16(cacc[nt], al0, al1, al2, al3, bh0, bh1);
                mma_bf16(cacc[nt], ah0, ah1, ah2, ah3, bl0, bl1);
            }
        }

        #pragma unroll
        for (int nt = 0; nt < 3; ++nt) {
            int col = nt * 8 + 2 * t;
            int idx = b * (TT * NE) + tr * NE + h * HS + col;
            uint32_t hp, lp;
            split2(cacc[nt][0], cacc[nt][1], hp, lp);
            *(uint32_t*)&g_chi[idx] = hp;
            *(uint32_t*)&g_clo[idx] = lp;
            split2(cacc[nt][2], cacc[nt][3], hp, lp);
            *(uint32_t*)&g_chi[idx + 8 * NE] = hp;
            *(uint32_t*)&g_clo[idx + 8 * NE] = lp;
        }
    }
}

// =====================================================================
extern "C" void kernel_launch(void* const* d_in, const int* in_sizes, int n_in,
                              void* d_out, int out_size)
{
    const float* x   = (const float*)d_in[0];
    const float* Wq  = (const float*)d_in[1];
    const float* Wk  = (const float*)d_in[2];
    const float* Wv  = (const float*)d_in[3];
    const float* rel = (const float*)d_in[4];
    const float* Wp  = (const float*)d_in[5];
    const float* bp  = (const float*)d_in[6];
    float* out = (float*)d_out;

    cudaFuncSetAttribute(qkv6_kernel,
                         cudaFuncAttributeMaxDynamicSharedMemorySize, GSM6);
    cudaFuncSetAttribute(proj6_kernel,
                         cudaFuncAttributeMaxDynamicSharedMemorySize, GSM6);
    cudaFuncSetAttribute(attn7_kernel,
                         cudaFuncAttributeMaxDynamicSharedMemorySize, ASMEM5);

    split_wr_kernel<<<dim3(81, 5), 256>>>(Wq, Wk, Wv, Wp, rel);

    qkv6_kernel<<<MTOT / 64, 256, GSM6>>>(x);

    attn7_kernel<<<BB * NH, 256, ASMEM5>>>();

    proj6_kernel<<<MTOT / 64, 256, GSM6>>>(bp, out);
}